// round 5
// baseline (speedup 1.0000x reference)
#include <cuda_runtime.h>
#include <math.h>

#define S   512
#define B   64
#define H   256
#define NH  4
#define NHH 1024      // NH*H
#define NCTA 128

// ---------------- device globals (no runtime allocation allowed) ------------
__device__ float g_P[(size_t)S * H * B];       // [t][j][b]  : x@Wi.T
__device__ float g_gate[(size_t)S * B * NH];   // [t][b][nh] : sigmoid gates
__device__ float g_cand[2][H * B];             // double-buffered cand, [j][b]
__device__ float g_sel[B * NHH];               // hcat at t = len-1
__device__ unsigned g_flags[NCTA];             // grid-barrier flags (4B stride)

// ---------------- init: reset barrier flags each replay ---------------------
__global__ void init_kernel() {
    int i = threadIdx.x;
    if (i < NCTA) g_flags[i] = 0u;
}

// ---------------- gate precompute: g = sigmoid(d - 3*nh) --------------------
__global__ __launch_bounds__(256)
void gate_kernel(const float* __restrict__ fix_src) {
    int t = blockIdx.x;
    int tid = threadIdx.x;          // b = tid>>2, nh = tid&3
    int b = tid >> 2, nh = tid & 3;
    float d = fix_src[b * S + t];
    g_gate[(size_t)t * (B * NH) + tid] = 1.0f / (1.0f + expf(3.0f * (float)nh - d));
}

// ---------------- P precompute: P[t][j][b] = emb[src[b,t]] . Wi[j,:] --------
__global__ __launch_bounds__(256, 2)
void p_kernel(const int* __restrict__ src, const float* __restrict__ emb,
              const float* __restrict__ Wi) {
    __shared__ float s_x[32][256];
    __shared__ int s_tok[32];
    const int t = blockIdx.x >> 1, bh = blockIdx.x & 1;
    const int tid = threadIdx.x;

    if (tid < 32) s_tok[tid] = src[(bh * 32 + tid) * S + t];
    __syncthreads();
    {
        int row = tid >> 3, seg = tid & 7;
        const float4* sp = (const float4*)(emb + (size_t)s_tok[row] * H) + seg * 8;
        float4* dp = (float4*)(&s_x[row][0]) + seg * 8;
        #pragma unroll
        for (int q = 0; q < 8; ++q) dp[q] = sp[q];
    }
    __syncthreads();

    float acc[32];
    #pragma unroll
    for (int m = 0; m < 32; ++m) acc[m] = 0.0f;
    const int j = tid;
    const float4* w4p = (const float4*)(Wi + (size_t)j * H);

    #pragma unroll 2
    for (int k4 = 0; k4 < 64; ++k4) {
        float4 wv = w4p[k4];
        #pragma unroll
        for (int m = 0; m < 32; ++m) {
            float4 xv = *(const float4*)&s_x[m][k4 * 4];
            acc[m] = fmaf(wv.x, xv.x, acc[m]);
            acc[m] = fmaf(wv.y, xv.y, acc[m]);
            acc[m] = fmaf(wv.z, xv.z, acc[m]);
            acc[m] = fmaf(wv.w, xv.w, acc[m]);
        }
    }
    float* out = g_P + (size_t)t * (H * B) + (size_t)j * B + bh * 32;
    #pragma unroll
    for (int m4 = 0; m4 < 8; ++m4)
        ((float4*)out)[m4] = make_float4(acc[m4 * 4], acc[m4 * 4 + 1],
                                         acc[m4 * 4 + 2], acc[m4 * 4 + 3]);
}

// ---------------- grid barrier: release store + vector poll -----------------
__device__ __forceinline__ void grid_barrier(unsigned& bcnt, int tid, int cid) {
    __syncthreads();                       // CTA arrival + cta-scope ordering
    ++bcnt;
    if (tid == 0) {
        asm volatile("st.release.gpu.global.u32 [%0], %1;"
                     :: "l"(&g_flags[cid]), "r"(bcnt) : "memory");
    }
    if (tid < NCTA / 4) {
        const uint4* fp = (const uint4*)g_flags;
        for (;;) {
            uint4 f;
            asm volatile("ld.volatile.global.v4.u32 {%0,%1,%2,%3}, [%4];"
                         : "=r"(f.x), "=r"(f.y), "=r"(f.z), "=r"(f.w)
                         : "l"(fp + tid) : "memory");
            if (f.x >= bcnt && f.y >= bcnt && f.z >= bcnt && f.w >= bcnt) break;
        }
        asm volatile("fence.acq_rel.gpu;" ::: "memory");
    }
    __syncthreads();                       // publish observation CTA-wide
}

// ---------------- persistent recurrent kernel -------------------------------
// 128 CTAs, CTA c owns output columns j = {2c, 2c+1}. 256 threads:
//   ks = tid>>7 (j'-split), jl = (tid>>6)&1, b = tid&63.
__global__ __launch_bounds__(256, 1)
void rnn_kernel(const int* __restrict__ input_len,
                const float* __restrict__ bi, const float* __restrict__ bhb,
                const float* __restrict__ Wh) {
    extern __shared__ float sm[];
    float* s_cand = sm;                  // [256][64]  64 KB
    float* s_Wp   = sm + 16384;          // packed Wh [j'][jl][nh], 8 KB
    float* s_y    = sm + 16384 + 2048;   // ks-reduce buffer, 2 KB

    const int tid = threadIdx.x, cid = blockIdx.x;
    const int ks = tid >> 7, jl = (tid >> 6) & 1, b = tid & 63;
    const int j = cid * 2 + jl;

    // pack Wh rows for our two j's: s_Wp[(j'*2 + jl)*4 + nh] = Wh[j, nh*256+j']
    for (int u = tid; u < 2048; u += 256) {
        int jp = u >> 3, ujl = (u >> 2) & 1, nh = u & 3;
        s_Wp[u] = Wh[(size_t)(cid * 2 + ujl) * NHH + nh * H + jp];
    }
    const unsigned wp_s = (unsigned)__cvta_generic_to_shared(s_Wp)
                        + (unsigned)((((ks << 7) << 3) + (jl << 2)) << 2);

    const float bsum = bi[j] + bhb[j];
    const int mylen = input_len[b];
    float z0 = 0.f, z1 = 0.f, z2 = 0.f, z3 = 0.f;
    float h0 = 0.f, h1 = 0.f, h2 = 0.f, h3 = 0.f;
    unsigned bcnt = 0;

    // cand(0) = tanh(P[0] + bias)   (z = 0)
    if (ks == 0)
        g_cand[0][j * B + b] = tanhf(g_P[(size_t)j * B + b] + bsum);
    grid_barrier(bcnt, tid, cid);        // also covers s_Wp staging

    #pragma unroll 1
    for (int t = 0; t < S; ++t) {
        const int p = t & 1;

        // prefetch next-step P and this-step gates (consumed after reduce)
        float pnext = (t < S - 1)
            ? g_P[(size_t)(t + 1) * (H * B) + (size_t)j * B + b] : 0.f;
        float4 g4 = *(const float4*)&g_gate[(size_t)t * (B * NH) + b * 4];

        // stage full cand [256][64] into smem (64 KB, coalesced)
        {
            const float4* gsrc = (const float4*)g_cand[p];
            float4* sdst = (float4*)s_cand;
            #pragma unroll
            for (int q = 0; q < 16; ++q)
                sdst[tid + q * 256] = gsrc[tid + q * 256];
        }
        __syncthreads();

        // y[j,nh] partials over our 128-j' slice: FFMA2 packed
        unsigned long long y01 = 0ULL, y23 = 0ULL;
        const float* cbase = s_cand + ((ks << 7) << 6) + b;
        #pragma unroll 8
        for (int i = 0; i < 128; ++i) {
            unsigned long long w01, w23, cvv;
            asm("ld.shared.v2.u64 {%0,%1}, [%2];"
                : "=l"(w01), "=l"(w23) : "r"(wp_s + i * 32));
            float cv = cbase[i * 64];
            asm("mov.b64 %0, {%1,%1};" : "=l"(cvv) : "r"(__float_as_uint(cv)));
            asm("fma.rn.f32x2 %0, %1, %2, %0;" : "+l"(y01) : "l"(w01), "l"(cvv));
            asm("fma.rn.f32x2 %0, %1, %2, %0;" : "+l"(y23) : "l"(w23), "l"(cvv));
        }
        float y0, y1, y2, y3;
        {
            unsigned lo, hi;
            asm("mov.b64 {%0,%1}, %2;" : "=r"(lo), "=r"(hi) : "l"(y01));
            y0 = __uint_as_float(lo); y1 = __uint_as_float(hi);
            asm("mov.b64 {%0,%1}, %2;" : "=r"(lo), "=r"(hi) : "l"(y23));
            y2 = __uint_as_float(lo); y3 = __uint_as_float(hi);
        }

        if (ks == 1)
            *(float4*)&s_y[(jl * 64 + b) * 4] = make_float4(y0, y1, y2, y3);
        __syncthreads();

        if (ks == 0) {
            float4 yo = *(const float4*)&s_y[(jl * 64 + b) * 4];
            y0 += yo.x; y1 += yo.y; y2 += yo.z; y3 += yo.w;

            float cl = s_cand[j * 64 + b];       // cand(t) for our own (b,j)

            z0 = fmaf(g4.x, y0 - z0, z0);        // z' = z + g*(y - z)
            z1 = fmaf(g4.y, y1 - z1, z1);
            z2 = fmaf(g4.z, y2 - z2, z2);
            z3 = fmaf(g4.w, y3 - z3, z3);
            h0 = fmaf(g4.x, cl - h0, h0);        // h' = h + g*(cand - h)
            h1 = fmaf(g4.y, cl - h1, h1);
            h2 = fmaf(g4.z, cl - h2, h2);
            h3 = fmaf(g4.w, cl - h3, h3);

            if (t == mylen - 1) {
                g_sel[b * NHH + 0 * H + j] = h0;
                g_sel[b * NHH + 1 * H + j] = h1;
                g_sel[b * NHH + 2 * H + j] = h2;
                g_sel[b * NHH + 3 * H + j] = h3;
            }
            if (t < S - 1)
                g_cand[p ^ 1][j * B + b] =
                    tanhf(pnext + bsum + z0 + z1 + z2 + z3);
        }
        grid_barrier(bcnt, tid, cid);
    }
}

// ---------------- readout ---------------------------------------------------
__global__ __launch_bounds__(256)
void final_fc_kernel(const float* __restrict__ fc1_W,
                     const float* __restrict__ fc1_b,
                     const float* __restrict__ fc2_W,
                     const float* __restrict__ fc2_b,
                     float* __restrict__ out) {
    __shared__ float selsh[NHH];
    __shared__ float red0[H];
    __shared__ float red1[H];
    const int b = blockIdx.x;
    const int j = threadIdx.x;

    #pragma unroll
    for (int i = 0; i < NH; ++i)
        selsh[i * H + j] = g_sel[b * NHH + i * H + j];
    __syncthreads();

    float s = fc1_b[j];
    const float4* w = (const float4*)(fc1_W + (size_t)j * NHH);
    #pragma unroll 4
    for (int k4 = 0; k4 < NHH / 4; ++k4) {
        float4 wv = w[k4];
        float4 sv = *(const float4*)&selsh[k4 * 4];
        s = fmaf(wv.x, sv.x, s);
        s = fmaf(wv.y, sv.y, s);
        s = fmaf(wv.z, sv.z, s);
        s = fmaf(wv.w, sv.w, s);
    }
    s = tanhf(s);
    red0[j] = s * fc2_W[j];
    red1[j] = s * fc2_W[H + j];
    __syncthreads();

    for (int stride = 128; stride >= 1; stride >>= 1) {
        if (j < stride) {
            red0[j] += red0[j + stride];
            red1[j] += red1[j + stride];
        }
        __syncthreads();
    }
    if (j == 0) {
        out[b * 2 + 0] = red0[0] + fc2_b[0];
        out[b * 2 + 1] = red1[0] + fc2_b[1];
    }
}

// ---------------------------------------------------------------------------
extern "C" void kernel_launch(void* const* d_in, const int* in_sizes, int n_in,
                              void* d_out, int out_size) {
    const int*   src       = (const int*)  d_in[0];
    const int*   input_len = (const int*)  d_in[1];
    const float* fix_src   = (const float*)d_in[2];
    const float* emb_table = (const float*)d_in[3];
    const float* Wi        = (const float*)d_in[4];
    const float* bi        = (const float*)d_in[5];
    const float* Wh        = (const float*)d_in[6];
    const float* bh        = (const float*)d_in[7];
    const float* fc1_W     = (const float*)d_in[8];
    const float* fc1_b     = (const float*)d_in[9];
    const float* fc2_W     = (const float*)d_in[10];
    const float* fc2_b     = (const float*)d_in[11];
    float* out = (float*)d_out;

    const int rnn_smem = (16384 + 2048 + 512) * 4;   // 75776 B
    cudaFuncSetAttribute(rnn_kernel,
                         cudaFuncAttributeMaxDynamicSharedMemorySize, rnn_smem);

    init_kernel<<<1, 128>>>();
    gate_kernel<<<S, 256>>>(fix_src);
    p_kernel<<<2 * S, 256>>>(src, emb_table, Wi);
    rnn_kernel<<<NCTA, 256, rnn_smem>>>(input_len, bi, bh, Wh);
    final_fc_kernel<<<B, 256>>>(fc1_W, fc1_b, fc2_W, fc2_b, out);
}

// round 6
// speedup vs baseline: 1.3867x; 1.3867x over previous
#include <cuda_runtime.h>
#include <math.h>

#define S   512
#define B   64
#define H   256
#define NH  4
#define NHH 1024      // NH*H
#define NCTA 128

// ---------------- device globals (no runtime allocation allowed) ------------
__device__ float g_P[(size_t)S * H * B];       // [t][j][b]  : x@Wi.T
__device__ float g_gate[(size_t)S * B * NH];   // [t][b][nh] : sigmoid gates
__device__ float g_cand[2][H * B];             // double-buffered cand, [j][b]
__device__ float g_sel[B * NHH];               // hcat at t = len-1
__device__ unsigned g_flags[NCTA];             // grid-barrier flags

// ---------------- init: reset barrier flags each replay ---------------------
__global__ void init_kernel() {
    int i = threadIdx.x;
    if (i < NCTA) g_flags[i] = 0u;
}

// ---------------- gate precompute: g = sigmoid(d - 3*nh) --------------------
__global__ __launch_bounds__(256)
void gate_kernel(const float* __restrict__ fix_src) {
    int t = blockIdx.x;
    int tid = threadIdx.x;          // b = tid>>2, nh = tid&3
    int b = tid >> 2, nh = tid & 3;
    float d = fix_src[b * S + t];
    g_gate[(size_t)t * (B * NH) + tid] = 1.0f / (1.0f + expf(3.0f * (float)nh - d));
}

// ---------------- P precompute: P[t][j][b] = emb[src[b,t]] . Wi[j,:] --------
__global__ __launch_bounds__(256, 2)
void p_kernel(const int* __restrict__ src, const float* __restrict__ emb,
              const float* __restrict__ Wi) {
    __shared__ float s_x[32][256];
    __shared__ int s_tok[32];
    const int t = blockIdx.x >> 1, bh = blockIdx.x & 1;
    const int tid = threadIdx.x;

    if (tid < 32) s_tok[tid] = src[(bh * 32 + tid) * S + t];
    __syncthreads();
    {
        int row = tid >> 3, seg = tid & 7;
        const float4* sp = (const float4*)(emb + (size_t)s_tok[row] * H) + seg * 8;
        float4* dp = (float4*)(&s_x[row][0]) + seg * 8;
        #pragma unroll
        for (int q = 0; q < 8; ++q) dp[q] = sp[q];
    }
    __syncthreads();

    float acc[32];
    #pragma unroll
    for (int m = 0; m < 32; ++m) acc[m] = 0.0f;
    const int j = tid;
    const float4* w4p = (const float4*)(Wi + (size_t)j * H);

    #pragma unroll 2
    for (int k4 = 0; k4 < 64; ++k4) {
        float4 wv = w4p[k4];
        #pragma unroll
        for (int m = 0; m < 32; ++m) {
            float4 xv = *(const float4*)&s_x[m][k4 * 4];
            acc[m] = fmaf(wv.x, xv.x, acc[m]);
            acc[m] = fmaf(wv.y, xv.y, acc[m]);
            acc[m] = fmaf(wv.z, xv.z, acc[m]);
            acc[m] = fmaf(wv.w, xv.w, acc[m]);
        }
    }
    float* out = g_P + (size_t)t * (H * B) + (size_t)j * B + bh * 32;
    #pragma unroll
    for (int m4 = 0; m4 < 8; ++m4)
        ((float4*)out)[m4] = make_float4(acc[m4 * 4], acc[m4 * 4 + 1],
                                         acc[m4 * 4 + 2], acc[m4 * 4 + 3]);
}

// ---------------- grid barrier (R3-proven structure, lighter backoff) -------
__device__ __forceinline__ void grid_barrier(unsigned& bcnt, int tid, int cid) {
    __syncthreads();                       // CTA arrival (cta-scope ordering)
    ++bcnt;
    if (tid == 0) {
        __threadfence();                   // order cand stores before flag
        *(volatile unsigned*)&g_flags[cid] = bcnt;
    }
    if (tid < NCTA) {
        while (*(volatile unsigned*)&g_flags[tid] < bcnt) __nanosleep(32);
        __threadfence();                   // acquire (pollers only)
    }
    __syncthreads();                       // publish observation CTA-wide
}

// ---------------- persistent recurrent kernel -------------------------------
// 128 CTAs, CTA c owns output columns j = {2c, 2c+1}. 512 threads:
//   ks = tid>>7 (4-way j'-split), jl = (tid>>6)&1, b = tid&63.
__global__ __launch_bounds__(512, 1)
void rnn_kernel(const int* __restrict__ input_len,
                const float* __restrict__ bi, const float* __restrict__ bhb,
                const float* __restrict__ Wh) {
    extern __shared__ float sm[];
    float* s_cand = sm;                  // [256][64]  64 KB
    float* s_Wp   = sm + 16384;          // packed Wh [j'][jl][nh], 8 KB
    float* s_y    = sm + 16384 + 2048;   // [ks][jl*64+b][nh] partials, 8 KB

    const int tid = threadIdx.x, cid = blockIdx.x;
    const int ks = tid >> 7, jl = (tid >> 6) & 1, b = tid & 63;
    const int j = cid * 2 + jl;

    // pack Wh rows for our two j's: s_Wp[(j'*2 + jl)*4 + nh] = Wh[j, nh*256+j']
    for (int u = tid; u < 2048; u += 512) {
        int jp = u >> 3, ujl = (u >> 2) & 1, nh = u & 3;
        s_Wp[u] = Wh[(size_t)(cid * 2 + ujl) * NHH + nh * H + jp];
    }

    const float bsum = bi[j] + bhb[j];
    const int mylen = input_len[b];
    float z0 = 0.f, z1 = 0.f, z2 = 0.f, z3 = 0.f;
    float h0 = 0.f, h1 = 0.f, h2 = 0.f, h3 = 0.f;
    unsigned bcnt = 0;

    // cand(0) = tanh(P[0] + bias)   (z = 0)
    if (ks == 0)
        g_cand[0][j * B + b] = tanhf(g_P[(size_t)j * B + b] + bsum);
    grid_barrier(bcnt, tid, cid);        // also covers s_Wp staging

    #pragma unroll 1
    for (int t = 0; t < S; ++t) {
        const int p = t & 1;

        // prefetch (ks==0 threads): next-step P and this-step gates
        float pnext = 0.0f;
        float4 g4 = make_float4(0.f, 0.f, 0.f, 0.f);
        if (ks == 0) {
            if (t < S - 1)
                pnext = g_P[(size_t)(t + 1) * (H * B) + (size_t)j * B + b];
            g4 = *(const float4*)&g_gate[(size_t)t * (B * NH) + b * 4];
        }

        // stage full cand [256][64] into smem (64 KB, L2-direct, coalesced)
        {
            const float4* gsrc = (const float4*)g_cand[p];
            float4* sdst = (float4*)s_cand;
            #pragma unroll
            for (int q = 0; q < 8; ++q)
                sdst[tid + q * 512] = __ldcg(gsrc + tid + q * 512);
        }
        __syncthreads();

        // y[j,nh] partials over our 64-j' slice
        float y0 = 0.f, y1 = 0.f, y2 = 0.f, y3 = 0.f;
        const float* wb = s_Wp + ks * 512 + jl * 4;
        const float* cb = s_cand + (ks << 6 << 6) + b;
        #pragma unroll 8
        for (int i = 0; i < 64; ++i) {
            float4 w4 = *(const float4*)(wb + i * 8);    // warp-broadcast
            float cv = cb[i * 64];                       // conflict-free
            y0 = fmaf(w4.x, cv, y0);
            y1 = fmaf(w4.y, cv, y1);
            y2 = fmaf(w4.z, cv, y2);
            y3 = fmaf(w4.w, cv, y3);
        }
        *(float4*)&s_y[(ks * 128 + jl * 64 + b) * 4] =
            make_float4(y0, y1, y2, y3);
        __syncthreads();

        if (ks == 0) {
            #pragma unroll
            for (int kk = 1; kk < 4; ++kk) {
                float4 yo = *(const float4*)&s_y[(kk * 128 + jl * 64 + b) * 4];
                y0 += yo.x; y1 += yo.y; y2 += yo.z; y3 += yo.w;
            }
            float cl = s_cand[j * 64 + b];       // cand(t) for our own (b,j)

            z0 = fmaf(g4.x, y0 - z0, z0);        // z' = z + g*(y - z)
            z1 = fmaf(g4.y, y1 - z1, z1);
            z2 = fmaf(g4.z, y2 - z2, z2);
            z3 = fmaf(g4.w, y3 - z3, z3);
            h0 = fmaf(g4.x, cl - h0, h0);        // h' = h + g*(cand - h)
            h1 = fmaf(g4.y, cl - h1, h1);
            h2 = fmaf(g4.z, cl - h2, h2);
            h3 = fmaf(g4.w, cl - h3, h3);

            if (t == mylen - 1) {
                g_sel[b * NHH + 0 * H + j] = h0;
                g_sel[b * NHH + 1 * H + j] = h1;
                g_sel[b * NHH + 2 * H + j] = h2;
                g_sel[b * NHH + 3 * H + j] = h3;
            }
            if (t < S - 1)
                g_cand[p ^ 1][j * B + b] =
                    tanhf(pnext + bsum + z0 + z1 + z2 + z3);
        }
        grid_barrier(bcnt, tid, cid);
    }
}

// ---------------- readout ---------------------------------------------------
__global__ __launch_bounds__(256)
void final_fc_kernel(const float* __restrict__ fc1_W,
                     const float* __restrict__ fc1_b,
                     const float* __restrict__ fc2_W,
                     const float* __restrict__ fc2_b,
                     float* __restrict__ out) {
    __shared__ float selsh[NHH];
    __shared__ float red0[H];
    __shared__ float red1[H];
    const int b = blockIdx.x;
    const int j = threadIdx.x;

    #pragma unroll
    for (int i = 0; i < NH; ++i)
        selsh[i * H + j] = g_sel[b * NHH + i * H + j];
    __syncthreads();

    float s = fc1_b[j];
    const float4* w = (const float4*)(fc1_W + (size_t)j * NHH);
    #pragma unroll 4
    for (int k4 = 0; k4 < NHH / 4; ++k4) {
        float4 wv = w[k4];
        float4 sv = *(const float4*)&selsh[k4 * 4];
        s = fmaf(wv.x, sv.x, s);
        s = fmaf(wv.y, sv.y, s);
        s = fmaf(wv.z, sv.z, s);
        s = fmaf(wv.w, sv.w, s);
    }
    s = tanhf(s);
    red0[j] = s * fc2_W[j];
    red1[j] = s * fc2_W[H + j];
    __syncthreads();

    for (int stride = 128; stride >= 1; stride >>= 1) {
        if (j < stride) {
            red0[j] += red0[j + stride];
            red1[j] += red1[j + stride];
        }
        __syncthreads();
    }
    if (j == 0) {
        out[b * 2 + 0] = red0[0] + fc2_b[0];
        out[b * 2 + 1] = red1[0] + fc2_b[1];
    }
}

// ---------------------------------------------------------------------------
extern "C" void kernel_launch(void* const* d_in, const int* in_sizes, int n_in,
                              void* d_out, int out_size) {
    const int*   src       = (const int*)  d_in[0];
    const int*   input_len = (const int*)  d_in[1];
    const float* fix_src   = (const float*)d_in[2];
    const float* emb_table = (const float*)d_in[3];
    const float* Wi        = (const float*)d_in[4];
    const float* bi        = (const float*)d_in[5];
    const float* Wh        = (const float*)d_in[6];
    const float* bh        = (const float*)d_in[7];
    const float* fc1_W     = (const float*)d_in[8];
    const float* fc1_b     = (const float*)d_in[9];
    const float* fc2_W     = (const float*)d_in[10];
    const float* fc2_b     = (const float*)d_in[11];
    float* out = (float*)d_out;

    const int rnn_smem = (16384 + 2048 + 2048) * 4;   // 81920 B
    cudaFuncSetAttribute(rnn_kernel,
                         cudaFuncAttributeMaxDynamicSharedMemorySize, rnn_smem);

    init_kernel<<<1, 128>>>();
    gate_kernel<<<S, 256>>>(fix_src);
    p_kernel<<<2 * S, 256>>>(src, emb_table, Wi);
    rnn_kernel<<<NCTA, 512, rnn_smem>>>(input_len, bi, bh, Wh);
    final_fc_kernel<<<B, 256>>>(fc1_W, fc1_b, fc2_W, fc2_b, out);
}

// round 7
// speedup vs baseline: 2.7376x; 1.9742x over previous
#include <cuda_runtime.h>
#include <math.h>

#define S   512
#define B   64
#define H   256
#define NH  4
#define NHH 1024      // NH*H
#define NCTA 128

// ---------------- device globals (no runtime allocation allowed) ------------
__device__ float g_P[(size_t)S * H * B];       // [t][j][b]  : x@Wi.T
__device__ float g_gate[(size_t)S * B * NH];   // [t][b][nh] : sigmoid gates
__device__ float g_cand[2][H * B];             // double-buffered cand, [j][b]
__device__ float g_sel[B * NHH];               // hcat at t = len-1
__device__ __align__(128) unsigned g_count;    // barrier arrival counter
__device__ __align__(128) unsigned g_epoch;    // barrier release epoch

// ---------------- init: reset barrier state each replay ---------------------
__global__ void init_kernel() {
    if (threadIdx.x == 0) { g_count = 0u; g_epoch = 0u; }
}

// ---------------- gate precompute: g = sigmoid(d - 3*nh) --------------------
__global__ __launch_bounds__(256)
void gate_kernel(const float* __restrict__ fix_src) {
    int t = blockIdx.x;
    int tid = threadIdx.x;          // b = tid>>2, nh = tid&3
    int b = tid >> 2, nh = tid & 3;
    float d = fix_src[b * S + t];
    g_gate[(size_t)t * (B * NH) + tid] = 1.0f / (1.0f + expf(3.0f * (float)nh - d));
}

// ---------------- P precompute: P[t][j][b] = emb[src[b,t]] . Wi[j,:] --------
__global__ __launch_bounds__(256, 2)
void p_kernel(const int* __restrict__ src, const float* __restrict__ emb,
              const float* __restrict__ Wi) {
    __shared__ float s_x[32][256];
    __shared__ int s_tok[32];
    const int t = blockIdx.x >> 1, bh = blockIdx.x & 1;
    const int tid = threadIdx.x;

    if (tid < 32) s_tok[tid] = src[(bh * 32 + tid) * S + t];
    __syncthreads();
    {
        int row = tid >> 3, seg = tid & 7;
        const float4* sp = (const float4*)(emb + (size_t)s_tok[row] * H) + seg * 8;
        float4* dp = (float4*)(&s_x[row][0]) + seg * 8;
        #pragma unroll
        for (int q = 0; q < 8; ++q) dp[q] = sp[q];
    }
    __syncthreads();

    float acc[32];
    #pragma unroll
    for (int m = 0; m < 32; ++m) acc[m] = 0.0f;
    const int j = tid;
    const float4* w4p = (const float4*)(Wi + (size_t)j * H);

    #pragma unroll 2
    for (int k4 = 0; k4 < 64; ++k4) {
        float4 wv = w4p[k4];
        #pragma unroll
        for (int m = 0; m < 32; ++m) {
            float4 xv = *(const float4*)&s_x[m][k4 * 4];
            acc[m] = fmaf(wv.x, xv.x, acc[m]);
            acc[m] = fmaf(wv.y, xv.y, acc[m]);
            acc[m] = fmaf(wv.z, xv.z, acc[m]);
            acc[m] = fmaf(wv.w, xv.w, acc[m]);
        }
    }
    float* out = g_P + (size_t)t * (H * B) + (size_t)j * B + bh * 32;
    #pragma unroll
    for (int m4 = 0; m4 < 8; ++m4)
        ((float4*)out)[m4] = make_float4(acc[m4 * 4], acc[m4 * 4 + 1],
                                         acc[m4 * 4 + 2], acc[m4 * 4 + 3]);
}

// ---------------- central-counter grid barrier (1 poller/CTA) ---------------
__device__ __forceinline__ void grid_barrier(unsigned& bcnt, int tid) {
    __syncthreads();                      // CTA arrival; cta-scope hb to tid0
    ++bcnt;
    if (tid == 0) {
        unsigned ret;
        asm volatile("atom.release.gpu.global.add.u32 %0, [%1], 1;"
                     : "=r"(ret) : "l"(&g_count) : "memory");
        if (ret == bcnt * NCTA - 1)       // last arriver of this phase
            asm volatile("st.release.gpu.global.u32 [%0], %1;"
                         :: "l"(&g_epoch), "r"(bcnt) : "memory");
        unsigned e;
        do {
            asm volatile("ld.acquire.gpu.global.u32 %0, [%1];"
                         : "=r"(e) : "l"(&g_epoch) : "memory");
        } while (e < bcnt);
    }
    __syncthreads();                      // release CTA; hb from tid0 acquire
}

// ---------------- persistent recurrent kernel -------------------------------
// 128 CTAs, CTA c owns output columns j = {2c, 2c+1}. 512 threads:
//   g = tid>>6 (8-way i-split, 32 cand rows each), b = tid&63.
//   Each thread accumulates BOTH jl outputs (8 accumulators) -> every cand
//   value is loaded exactly once per CTA, straight from L2 (no smem staging).
__global__ __launch_bounds__(512, 1)
void rnn_kernel(const int* __restrict__ input_len,
                const float* __restrict__ bi, const float* __restrict__ bhb,
                const float* __restrict__ Wh) {
    __shared__ float s_Wp[256 * 8];     // [i][jl][nh]  8 KB
    __shared__ float s_y[8 * 128 * 4];  // [g][jl*64+b][nh]  16 KB

    const int tid = threadIdx.x, cid = blockIdx.x;
    const int g = tid >> 6, b = tid & 63;
    const int jl = (tid >> 6) & 1;          // valid for tail threads (tid<128)
    const int j = cid * 2 + jl;

    // pack Wh: s_Wp[i*8 + jl*4 + nh] = Wh[2c+jl][nh*256 + i]
    for (int u = tid; u < 2048; u += 512) {
        int i = u >> 3, ujl = (u >> 2) & 1, nh = u & 3;
        s_Wp[u] = Wh[(size_t)(cid * 2 + ujl) * NHH + nh * H + i];
    }

    float bsum = 0.f;
    int mylen = 0;
    if (tid < 128) {
        bsum = bi[j] + bhb[j];
        mylen = input_len[b];
        // cand(0) = tanh(P[0] + bias)   (z = 0)
        g_cand[0][j * B + b] = tanhf(g_P[(size_t)j * B + b] + bsum);
    }
    float z0 = 0.f, z1 = 0.f, z2 = 0.f, z3 = 0.f;
    float h0 = 0.f, h1 = 0.f, h2 = 0.f, h3 = 0.f;
    unsigned bcnt = 0;

    grid_barrier(bcnt, tid);             // also covers s_Wp staging

    #pragma unroll 1
    for (int t = 0; t < S; ++t) {
        const int p = t & 1;
        const float* cand = g_cand[p];

        // tail-thread prefetches (consumed after the mid sync)
        float pnext = 0.0f, cl = 0.0f;
        float4 g4 = make_float4(0.f, 0.f, 0.f, 0.f);
        if (tid < 128) {
            if (t < S - 1)
                pnext = g_P[(size_t)(t + 1) * (H * B) + (size_t)j * B + b];
            g4 = *(const float4*)&g_gate[(size_t)t * (B * NH) + b * 4];
            cl = __ldcg(cand + j * B + b);
        }

        // partial y over our 32 cand rows, both jl at once
        float a0 = 0.f, a1 = 0.f, a2 = 0.f, a3 = 0.f;   // jl = 0
        float c0 = 0.f, c1 = 0.f, c2 = 0.f, c3 = 0.f;   // jl = 1
        const float* cb = cand + (g << 5) * B + b;
        const float4* wb = (const float4*)&s_Wp[(g << 5) * 8];
        #pragma unroll 8
        for (int k = 0; k < 32; ++k) {
            float cv = __ldcg(cb + k * B);
            float4 wA = wb[k * 2];          // warp-broadcast
            float4 wB = wb[k * 2 + 1];
            a0 = fmaf(wA.x, cv, a0); a1 = fmaf(wA.y, cv, a1);
            a2 = fmaf(wA.z, cv, a2); a3 = fmaf(wA.w, cv, a3);
            c0 = fmaf(wB.x, cv, c0); c1 = fmaf(wB.y, cv, c1);
            c2 = fmaf(wB.z, cv, c2); c3 = fmaf(wB.w, cv, c3);
        }
        *(float4*)&s_y[(g * 128 + b) * 4]      = make_float4(a0, a1, a2, a3);
        *(float4*)&s_y[(g * 128 + 64 + b) * 4] = make_float4(c0, c1, c2, c3);
        __syncthreads();

        if (tid < 128) {
            float y0 = 0.f, y1 = 0.f, y2 = 0.f, y3 = 0.f;
            #pragma unroll
            for (int gg = 0; gg < 8; ++gg) {
                float4 yv = *(const float4*)&s_y[(gg * 128 + jl * 64 + b) * 4];
                y0 += yv.x; y1 += yv.y; y2 += yv.z; y3 += yv.w;
            }
            z0 = fmaf(g4.x, y0 - z0, z0);        // z' = z + g*(y - z)
            z1 = fmaf(g4.y, y1 - z1, z1);
            z2 = fmaf(g4.z, y2 - z2, z2);
            z3 = fmaf(g4.w, y3 - z3, z3);
            h0 = fmaf(g4.x, cl - h0, h0);        // h' = h + g*(cand - h)
            h1 = fmaf(g4.y, cl - h1, h1);
            h2 = fmaf(g4.z, cl - h2, h2);
            h3 = fmaf(g4.w, cl - h3, h3);

            if (t == mylen - 1) {
                g_sel[b * NHH + 0 * H + j] = h0;
                g_sel[b * NHH + 1 * H + j] = h1;
                g_sel[b * NHH + 2 * H + j] = h2;
                g_sel[b * NHH + 3 * H + j] = h3;
            }
            if (t < S - 1)
                __stcg(&g_cand[p ^ 1][j * B + b],
                       tanhf(pnext + bsum + z0 + z1 + z2 + z3));
        }
        grid_barrier(bcnt, tid);
    }
}

// ---------------- readout ---------------------------------------------------
__global__ __launch_bounds__(256)
void final_fc_kernel(const float* __restrict__ fc1_W,
                     const float* __restrict__ fc1_b,
                     const float* __restrict__ fc2_W,
                     const float* __restrict__ fc2_b,
                     float* __restrict__ out) {
    __shared__ float selsh[NHH];
    __shared__ float red0[H];
    __shared__ float red1[H];
    const int b = blockIdx.x;
    const int j = threadIdx.x;

    #pragma unroll
    for (int i = 0; i < NH; ++i)
        selsh[i * H + j] = g_sel[b * NHH + i * H + j];
    __syncthreads();

    float s = fc1_b[j];
    const float4* w = (const float4*)(fc1_W + (size_t)j * NHH);
    #pragma unroll 4
    for (int k4 = 0; k4 < NHH / 4; ++k4) {
        float4 wv = w[k4];
        float4 sv = *(const float4*)&selsh[k4 * 4];
        s = fmaf(wv.x, sv.x, s);
        s = fmaf(wv.y, sv.y, s);
        s = fmaf(wv.z, sv.z, s);
        s = fmaf(wv.w, sv.w, s);
    }
    s = tanhf(s);
    red0[j] = s * fc2_W[j];
    red1[j] = s * fc2_W[H + j];
    __syncthreads();

    for (int stride = 128; stride >= 1; stride >>= 1) {
        if (j < stride) {
            red0[j] += red0[j + stride];
            red1[j] += red1[j + stride];
        }
        __syncthreads();
    }
    if (j == 0) {
        out[b * 2 + 0] = red0[0] + fc2_b[0];
        out[b * 2 + 1] = red1[0] + fc2_b[1];
    }
}

// ---------------------------------------------------------------------------
extern "C" void kernel_launch(void* const* d_in, const int* in_sizes, int n_in,
                              void* d_out, int out_size) {
    const int*   src       = (const int*)  d_in[0];
    const int*   input_len = (const int*)  d_in[1];
    const float* fix_src   = (const float*)d_in[2];
    const float* emb_table = (const float*)d_in[3];
    const float* Wi        = (const float*)d_in[4];
    const float* bi        = (const float*)d_in[5];
    const float* Wh        = (const float*)d_in[6];
    const float* bh        = (const float*)d_in[7];
    const float* fc1_W     = (const float*)d_in[8];
    const float* fc1_b     = (const float*)d_in[9];
    const float* fc2_W     = (const float*)d_in[10];
    const float* fc2_b     = (const float*)d_in[11];
    float* out = (float*)d_out;

    init_kernel<<<1, 32>>>();
    gate_kernel<<<S, 256>>>(fix_src);
    p_kernel<<<2 * S, 256>>>(src, emb_table, Wi);
    rnn_kernel<<<NCTA, 512>>>(input_len, bi, bh, Wh);
    final_fc_kernel<<<B, 256>>>(fc1_W, fc1_b, fc2_W, fc2_b, out);
}